// round 4
// baseline (speedup 1.0000x reference)
#include <cuda_runtime.h>

// PathGuidedAggregator:
//   out[i,:] = (deg[i] <= 5) ? (sum_{e: rows[e]==i} embeds[cols[e],:]) / max(count_i,1) : 0
// NOTE: JAX x64 is disabled in the reference, so node_degrees/path_rows/path_cols
// are int32 despite the dtype=jnp.int64 in the source. rows is SORTED -> per-row
// edge range via binary search. Mask-first: ~85% of rows (deg > 5) write zeros only.

#define EMBED_DIM 128
#define SPARSE_THRESHOLD 5

__global__ void __launch_bounds__(EMBED_DIM)
path_agg_kernel(const float* __restrict__ embeds,
                const int* __restrict__ degrees,
                const int* __restrict__ rows,
                const int* __restrict__ cols,
                float* __restrict__ out,
                int n_edges) {
    const int row = blockIdx.x;
    const int d = threadIdx.x;
    const size_t out_idx = (size_t)row * EMBED_DIM + d;

    // Mask-first: most blocks write a zero row and leave.
    if (__ldg(&degrees[row]) > SPARSE_THRESHOLD) {
        out[out_idx] = 0.0f;
        return;
    }

    // Threads 0 and 1 run the two binary searches in parallel:
    // t0: lower_bound(row) -> start, t1: lower_bound(row+1) -> end.
    __shared__ int s_bound[2];
    if (d < 2) {
        const int key = row + d;   // d==0: row, d==1: row+1
        int lo = 0, hi = n_edges;
        while (lo < hi) {
            int mid = (lo + hi) >> 1;
            if (__ldg(&rows[mid]) < key) lo = mid + 1; else hi = mid;
        }
        s_bound[d] = lo;
    }
    __syncthreads();

    const int start = s_bound[0];
    const int end   = s_bound[1];

    // Accumulate embeds[cols[e], d] over the edge range.
    // Unroll x4 with batched column loads for MLP (hides L2 latency + PTW).
    float acc0 = 0.0f, acc1 = 0.0f, acc2 = 0.0f, acc3 = 0.0f;
    int e = start;
    for (; e + 3 < end; e += 4) {
        int c0 = __ldg(&cols[e + 0]);
        int c1 = __ldg(&cols[e + 1]);
        int c2 = __ldg(&cols[e + 2]);
        int c3 = __ldg(&cols[e + 3]);
        acc0 += __ldg(&embeds[(size_t)c0 * EMBED_DIM + d]);
        acc1 += __ldg(&embeds[(size_t)c1 * EMBED_DIM + d]);
        acc2 += __ldg(&embeds[(size_t)c2 * EMBED_DIM + d]);
        acc3 += __ldg(&embeds[(size_t)c3 * EMBED_DIM + d]);
    }
    for (; e < end; ++e) {
        int c = __ldg(&cols[e]);
        acc0 += __ldg(&embeds[(size_t)c * EMBED_DIM + d]);
    }
    float acc = (acc0 + acc1) + (acc2 + acc3);

    const int cnt = end - start;
    const float inv = 1.0f / (float)(cnt > 0 ? cnt : 1);
    out[out_idx] = acc * inv;
}

extern "C" void kernel_launch(void* const* d_in, const int* in_sizes, int n_in,
                              void* d_out, int out_size) {
    const float* embeds  = (const float*)d_in[0];  // [N_ENT, 128] fp32
    const int*   degrees = (const int*)d_in[1];    // [N_ENT] int32 (JAX x64 off)
    const int*   rows    = (const int*)d_in[2];    // [N_EDGES] int32, sorted
    const int*   cols    = (const int*)d_in[3];    // [N_EDGES] int32
    float*       out     = (float*)d_out;          // [N_ENT, 128] fp32

    const int n_ent   = in_sizes[1];
    const int n_edges = in_sizes[2];

    path_agg_kernel<<<n_ent, EMBED_DIM>>>(embeds, degrees, rows, cols, out, n_edges);
}

// round 5
// speedup vs baseline: 1.5797x; 1.5797x over previous
#include <cuda_runtime.h>

// PathGuidedAggregator:
//   out[i,:] = (deg[i] <= 5) ? (sum_{e: rows[e]==i} embeds[cols[e],:]) / max(count_i,1) : 0
// Inputs are int32 (JAX x64 disabled). rows is SORTED.
// R4 redesign: CSR boundary precompute (kills the per-block binary-search
// dependent-load chain) + smem-staged cols with 8-way accumulators (MLP up).

#define EMBED_DIM 128
#define SPARSE_THRESHOLD 5
#define MAX_ENT 100000

// Scratch (allocation-free rule: __device__ globals)
__device__ int g_start[MAX_ENT];
__device__ int g_end[MAX_ENT];

__global__ void init_ptrs_kernel(int n_ent) {
    int i = blockIdx.x * blockDim.x + threadIdx.x;
    if (i < n_ent) { g_start[i] = 0; g_end[i] = 0; }
}

// Boundary scatter over sorted rows: first/last occurrence of each row value.
__global__ void boundaries_kernel(const int* __restrict__ rows, int n_edges) {
    int e = blockIdx.x * blockDim.x + threadIdx.x;
    if (e >= n_edges) return;
    int r = __ldg(&rows[e]);
    if (e == 0 || __ldg(&rows[e - 1]) != r) g_start[r] = e;
    if (e == n_edges - 1 || __ldg(&rows[e + 1]) != r) g_end[r] = e + 1;
}

__global__ void __launch_bounds__(EMBED_DIM)
path_agg_kernel(const float* __restrict__ embeds,
                const int* __restrict__ degrees,
                const int* __restrict__ cols,
                float* __restrict__ out) {
    const int row = blockIdx.x;
    const int d = threadIdx.x;
    const size_t out_idx = (size_t)row * EMBED_DIM + d;

    // Mask-first: ~85% of blocks write a zero row and leave.
    if (__ldg(&degrees[row]) > SPARSE_THRESHOLD) {
        out[out_idx] = 0.0f;
        return;
    }

    const int start = g_start[row];
    const int end   = g_end[row];

    __shared__ int s_cols[EMBED_DIM];

    float a0 = 0.f, a1 = 0.f, a2 = 0.f, a3 = 0.f;
    float a4 = 0.f, a5 = 0.f, a6 = 0.f, a7 = 0.f;

    for (int base = start; base < end; base += EMBED_DIM) {
        const int m = min(EMBED_DIM, end - base);
        if (d < m) s_cols[d] = __ldg(&cols[base + d]);
        __syncthreads();

        int k = 0;
        for (; k + 7 < m; k += 8) {
            int c0 = s_cols[k + 0], c1 = s_cols[k + 1];
            int c2 = s_cols[k + 2], c3 = s_cols[k + 3];
            int c4 = s_cols[k + 4], c5 = s_cols[k + 5];
            int c6 = s_cols[k + 6], c7 = s_cols[k + 7];
            a0 += __ldg(&embeds[(size_t)c0 * EMBED_DIM + d]);
            a1 += __ldg(&embeds[(size_t)c1 * EMBED_DIM + d]);
            a2 += __ldg(&embeds[(size_t)c2 * EMBED_DIM + d]);
            a3 += __ldg(&embeds[(size_t)c3 * EMBED_DIM + d]);
            a4 += __ldg(&embeds[(size_t)c4 * EMBED_DIM + d]);
            a5 += __ldg(&embeds[(size_t)c5 * EMBED_DIM + d]);
            a6 += __ldg(&embeds[(size_t)c6 * EMBED_DIM + d]);
            a7 += __ldg(&embeds[(size_t)c7 * EMBED_DIM + d]);
        }
        for (; k < m; ++k) {
            int c = s_cols[k];
            a0 += __ldg(&embeds[(size_t)c * EMBED_DIM + d]);
        }
        __syncthreads();
    }

    const float acc = ((a0 + a1) + (a2 + a3)) + ((a4 + a5) + (a6 + a7));
    const int cnt = end - start;
    const float inv = 1.0f / (float)(cnt > 0 ? cnt : 1);
    out[out_idx] = acc * inv;
}

extern "C" void kernel_launch(void* const* d_in, const int* in_sizes, int n_in,
                              void* d_out, int out_size) {
    const float* embeds  = (const float*)d_in[0];  // [N_ENT, 128] fp32
    const int*   degrees = (const int*)d_in[1];    // [N_ENT] int32
    const int*   rows    = (const int*)d_in[2];    // [N_EDGES] int32, sorted
    const int*   cols    = (const int*)d_in[3];    // [N_EDGES] int32
    float*       out     = (float*)d_out;          // [N_ENT, 128] fp32

    const int n_ent   = in_sizes[1];
    const int n_edges = in_sizes[2];

    init_ptrs_kernel<<<(n_ent + 255) / 256, 256>>>(n_ent);
    boundaries_kernel<<<(n_edges + 255) / 256, 256>>>(rows, n_edges);
    path_agg_kernel<<<n_ent, EMBED_DIM>>>(embeds, degrees, cols, out);
}